// round 4
// baseline (speedup 1.0000x reference)
#include <cuda_runtime.h>
#include <cstdint>

// ---------------------------------------------------------------------------
// Fused poker-feature + 2-layer MLP kernel, fp32 with packed f32x2 FMA.
//
//   out[B,256] = relu(x @ W1 + b1) @ W2 + b2
//   x = [hole(52) | board(52) | feats(15)]  -- first 104 cols are 0/1 bits
//
// Per block: 128 rows. Hidden dim processed in 8 chunks of 128 so the
// intermediate h never leaves shared memory. Stage 1 exploits sparsity
// (sum of ~6 W1 rows + 15 feature FMAs). Stage 2 is a classic smem GEMM
// with 8x8 micro-tiles using fma.rn.f32x2 (2 MACs/lane/instr).
// ---------------------------------------------------------------------------

#define BM        128
#define THREADS   512
#define IN_DIM    119
#define HIDDEN    1024
#define OUTD      256
#define NCHUNK    8       // 1024 / 128
#define HT_STRIDE 132     // 128 rows + 4 pad floats

// shared memory layout (float offsets)
#define HT_OFF    0
#define W1C_OFF   (128 * HT_STRIDE)          // 16896
#define B1C_OFF   (W1C_OFF + IN_DIM * 128)   // 32128
#define WS_OFF    (B1C_OFF + 128)            // 32256
#define FEAT_OFF  (WS_OFF + 32 * 256)        // 40448
#define CNT_OFF   (FEAT_OFF + 128 * 16)      // 42496
#define IDX_OFF   (CNT_OFF + 128)            // 42624 (bytes start here)
#define SMEM_BYTES (IDX_OFF * 4 + 128 * 104) // 183808 bytes

typedef unsigned long long u64;

__device__ __forceinline__ u64 dup2(float x) {
    unsigned u = __float_as_uint(x);
    u64 r;
    asm("mov.b64 %0, {%1, %2};" : "=l"(r) : "r"(u), "r"(u));
    return r;
}
__device__ __forceinline__ void ffma2(u64& d, u64 a, u64 b) {
    asm("fma.rn.f32x2 %0, %1, %2, %0;" : "+l"(d) : "l"(a), "l"(b));
}
__device__ __forceinline__ float2 unpk(u64 v) {
    unsigned lo, hi;
    asm("mov.b64 {%0, %1}, %2;" : "=r"(lo), "=r"(hi) : "l"(v));
    float2 f; f.x = __uint_as_float(lo); f.y = __uint_as_float(hi);
    return f;
}

// ---------------------------------------------------------------------------
// Per-row poker feature computation (matches reference exactly).
// ---------------------------------------------------------------------------
__device__ void compute_row_features(const float* __restrict__ hp,
                                     const float* __restrict__ bp,
                                     uint8_t* __restrict__ sidxr,
                                     int* __restrict__ cntOut,
                                     float* __restrict__ featOut)
{
    int cnt = 0;
    int bsc[4] = {0, 0, 0, 0};
    int asc[4] = {0, 0, 0, 0};
    int bcount = 0, hcount = 0;
    int pairs_b = 0, pairs_a = 0;
    bool trips_b = false, trips_a = false;
    int pb[17], pa[17];

#pragma unroll
    for (int rk = 0; rk < 13; rk++) {
        int b4 = 0, a4 = 0;
#pragma unroll
        for (int su = 0; su < 4; su++) {
            int c = rk * 4 + su;
            int hv = (hp[c] != 0.0f);
            int bv = (bp[c] != 0.0f);
            if (hv) sidxr[cnt++] = (uint8_t)c;
            if (bv) sidxr[cnt++] = (uint8_t)(52 + c);
            b4 += bv; a4 += hv + bv;
            bcount += bv; hcount += hv;
            bsc[su] += bv; asc[su] += hv + bv;
        }
        pairs_b += (b4 >= 2); trips_b |= (b4 >= 3);
        pairs_a += (a4 >= 2); trips_a |= (a4 >= 3);
        pb[rk] = (b4 > 0);
        pa[rk] = (a4 > 0);
    }
#pragma unroll
    for (int i = 13; i < 17; i++) { pb[i] = 0; pa[i] = 0; }

    float strength = trips_b ? 0.8f : (pairs_b >= 2 ? 0.6f : (pairs_b >= 1 ? 0.4f : 0.2f));
    if (bcount == 0) strength = 0.0f;

    int maxbsc = max(max(bsc[0], bsc[1]), max(bsc[2], bsc[3]));
    float flush_b = (maxbsc >= 3 && bcount > 0) ? 1.0f : 0.0f;

    bool sb = false;
#pragma unroll
    for (int j = 0; j < 13; j++) {
        int w = pb[j] + pb[j + 1] + pb[j + 2] + pb[j + 3] + pb[j + 4];
        if (w >= 3) sb = true;
    }
    float straight_b = (sb && bcount > 0) ? 1.0f : 0.0f;

    float g0 = (bcount == 0) ? 1.0f : 0.0f;
    float g3 = (bcount == 3) ? 1.0f : 0.0f;
    float g4 = (bcount == 4) ? 1.0f : 0.0f;
    float g5 = (bcount == 5) ? 1.0f : 0.0f;

    float valid = (hcount >= 2 && bcount >= 1) ? 1.0f : 0.0f;

    int msc = max(max(asc[0], asc[1]), max(asc[2], asc[3]));
    float flush_draw = (msc == 4) ? 1.0f : 0.0f;
    float flush_outs = fmaxf(0.0f, 13.0f - (float)msc) / 13.0f;

    bool found = false;
    int c4_at = 0;
#pragma unroll
    for (int j = 0; j < 13; j++) {
        int c5 = pa[j] + pa[j + 1] + pa[j + 2] + pa[j + 3] + pa[j + 4];
        bool q = (pa[j] > 0) && (c5 >= 4);
        if (q && !found) {
            found = true;
            c4_at = pa[j] + pa[j + 1] + pa[j + 2] + pa[j + 3];
        }
    }
    float sd = found ? 1.0f : 0.0f;
    float so = found ? (c4_at >= 4 ? 0.4f : 0.2f) : 0.0f;

    float total_outs = flush_draw * flush_outs * 9.0f + sd * so * 8.0f;
    float remaining = 52.0f - (float)(hcount + bcount);
    float equity = (remaining > 0.0f)
                       ? fminf(1.0f, total_outs / fmaxf(remaining, 1.0f))
                       : 0.0f;

    float hit_pair  = (pairs_a >= 1) ? 1.0f : 0.0f;
    float hit_trips = trips_a ? 1.0f : 0.0f;
    float hit_two   = (pairs_a >= 2) ? 1.0f : 0.0f;

    featOut[0]  = strength;
    featOut[1]  = flush_b;
    featOut[2]  = straight_b;
    featOut[3]  = g0;
    featOut[4]  = g3;
    featOut[5]  = g4;
    featOut[6]  = g5;
    featOut[7]  = valid * flush_draw;
    featOut[8]  = valid * flush_outs;
    featOut[9]  = valid * sd;
    featOut[10] = valid * so;
    featOut[11] = valid * equity;
    featOut[12] = valid * hit_pair;
    featOut[13] = valid * hit_trips;
    featOut[14] = valid * hit_two;
    *cntOut = cnt;
}

// ---------------------------------------------------------------------------
// Main fused kernel
// ---------------------------------------------------------------------------
__global__ void __launch_bounds__(THREADS, 1)
poker_mlp_kernel(const float* __restrict__ hole,
                 const float* __restrict__ board,
                 const float* __restrict__ W1,
                 const float* __restrict__ b1,
                 const float* __restrict__ W2,
                 const float* __restrict__ b2,
                 float* __restrict__ out,
                 int Btot)
{
    extern __shared__ float sm[];
    float*   sHT   = sm + HT_OFF;
    float*   sW1c  = sm + W1C_OFF;
    float*   sb1   = sm + B1C_OFF;
    float*   sws   = sm + WS_OFF;
    float*   sfeat = sm + FEAT_OFF;
    int*     scnt  = (int*)(sm + CNT_OFF);
    uint8_t* sidx  = (uint8_t*)(sm + IDX_OFF);

    const int tid  = threadIdx.x;
    const int row0 = blockIdx.x * BM;

    // ---- Phase 0: per-row features + sparse card index lists --------------
    if (tid < BM) {
        int r = tid;
        int grow = row0 + r;
        if (grow < Btot) {
            compute_row_features(hole + (size_t)grow * 52,
                                 board + (size_t)grow * 52,
                                 sidx + r * 104, &scnt[r], sfeat + r * 16);
        } else {
            scnt[r] = 0;
#pragma unroll
            for (int t = 0; t < 15; t++) sfeat[r * 16 + t] = 0.0f;
        }
    }
    __syncthreads();

    // ---- Stage-2 accumulators: 8 rows x 8 cols per thread (as 8x4 f32x2) --
    const int col_t = tid & 31;   // 32 col-threads: cols col_t*8 .. +8
    const int row_t = tid >> 5;   // 16 row-threads: rows row_t*8 .. +8
    u64 acc[8][4];
#pragma unroll
    for (int r = 0; r < 8; r++)
#pragma unroll
        for (int p = 0; p < 4; p++) acc[r][p] = 0ULL;

    const float4* W1c4 = (const float4*)sW1c;

    for (int chunk = 0; chunk < NCHUNK; chunk++) {
        // ---- stage W1 chunk (119x128) + b1 chunk into smem ----------------
        const int cb4 = chunk * 32;  // float4 column base
        for (int i = tid; i < IN_DIM * 32; i += THREADS) {
            int rw = i >> 5, c4 = i & 31;
            ((float4*)sW1c)[i] = ((const float4*)W1)[rw * 256 + cb4 + c4];
        }
        if (tid < 32)
            ((float4*)sb1)[tid] = ((const float4*)b1)[cb4 + tid];
        __syncthreads();

        // ---- Stage 1: h_chunk via sparse gather, stored transposed --------
        {
            const int j4 = tid & 31;  // float4 column within chunk
            const int rg = tid >> 5;  // 16 groups x 8 rows
            float4 bia = ((const float4*)sb1)[j4];
            for (int rr = 0; rr < 8; rr++) {
                int r = rg * 8 + rr;
                float4 a = bia;
                int cnt = scnt[r];
                const uint8_t* si = sidx + r * 104;
                for (int i = 0; i < cnt; i++) {
                    int ix = si[i];
                    float4 w = W1c4[ix * 32 + j4];
                    a.x += w.x; a.y += w.y; a.z += w.z; a.w += w.w;
                }
                const float* fr = sfeat + r * 16;
#pragma unroll
                for (int t = 0; t < 15; t++) {
                    float f = fr[t];
                    float4 w = W1c4[(104 + t) * 32 + j4];
                    a.x = fmaf(f, w.x, a.x);
                    a.y = fmaf(f, w.y, a.y);
                    a.z = fmaf(f, w.z, a.z);
                    a.w = fmaf(f, w.w, a.w);
                }
                a.x = fmaxf(a.x, 0.0f);
                a.y = fmaxf(a.y, 0.0f);
                a.z = fmaxf(a.z, 0.0f);
                a.w = fmaxf(a.w, 0.0f);
                int j = j4 * 4;
                sHT[(j + 0) * HT_STRIDE + r] = a.x;
                sHT[(j + 1) * HT_STRIDE + r] = a.y;
                sHT[(j + 2) * HT_STRIDE + r] = a.z;
                sHT[(j + 3) * HT_STRIDE + r] = a.w;
            }
        }
        __syncthreads();

        // ---- Stage 2: out += h_chunk @ W2_chunk, K-subtiles of 32 ---------
        for (int s = 0; s < 4; s++) {
            const int kbase = chunk * 128 + s * 32;
            for (int i = tid; i < 32 * 64; i += THREADS) {
                int k = i >> 6, n4 = i & 63;
                ((float4*)sws)[i] = ((const float4*)W2)[(kbase + k) * 64 + n4];
            }
            __syncthreads();

            const float* hbase = sHT + (s * 32) * HT_STRIDE + row_t * 8;
            const char*  wbase = (const char*)sws + col_t * 32;
#pragma unroll 4
            for (int kk = 0; kk < 32; kk++) {
                const float4* ap = (const float4*)(hbase + kk * HT_STRIDE);
                float4 a0 = ap[0];
                float4 a1 = ap[1];
                ulonglong2 w0 = *(const ulonglong2*)(wbase + kk * 1024);
                ulonglong2 w1 = *(const ulonglong2*)(wbase + kk * 1024 + 16);
                u64 ad[8];
                ad[0] = dup2(a0.x); ad[1] = dup2(a0.y);
                ad[2] = dup2(a0.z); ad[3] = dup2(a0.w);
                ad[4] = dup2(a1.x); ad[5] = dup2(a1.y);
                ad[6] = dup2(a1.z); ad[7] = dup2(a1.w);
#pragma unroll
                for (int r = 0; r < 8; r++) {
                    ffma2(acc[r][0], ad[r], w0.x);
                    ffma2(acc[r][1], ad[r], w0.y);
                    ffma2(acc[r][2], ad[r], w1.x);
                    ffma2(acc[r][3], ad[r], w1.y);
                }
            }
            __syncthreads();
        }
    }

    // ---- Epilogue: add b2, write out --------------------------------------
    const int col0 = col_t * 8;
    float4 bb0 = ((const float4*)b2)[col_t * 2];
    float4 bb1 = ((const float4*)b2)[col_t * 2 + 1];
#pragma unroll
    for (int rr = 0; rr < 8; rr++) {
        int grow = row0 + row_t * 8 + rr;
        if (grow >= Btot) continue;
        float2 p0 = unpk(acc[rr][0]);
        float2 p1 = unpk(acc[rr][1]);
        float2 p2 = unpk(acc[rr][2]);
        float2 p3 = unpk(acc[rr][3]);
        float4 o0 = make_float4(p0.x + bb0.x, p0.y + bb0.y,
                                p1.x + bb0.z, p1.y + bb0.w);
        float4 o1 = make_float4(p2.x + bb1.x, p2.y + bb1.y,
                                p3.x + bb1.z, p3.y + bb1.w);
        float4* op = (float4*)(out + (size_t)grow * OUTD + col0);
        op[0] = o0;
        op[1] = o1;
    }
}

// ---------------------------------------------------------------------------
extern "C" void kernel_launch(void* const* d_in, const int* in_sizes, int n_in,
                              void* d_out, int out_size)
{
    const float* hole  = (const float*)d_in[0];
    const float* board = (const float*)d_in[1];
    const float* W1    = (const float*)d_in[2];
    const float* b1    = (const float*)d_in[3];
    const float* W2    = (const float*)d_in[4];
    const float* b2    = (const float*)d_in[5];
    float* out = (float*)d_out;

    int B = in_sizes[0] / 52;
    int blocks = (B + BM - 1) / BM;

    cudaFuncSetAttribute(poker_mlp_kernel,
                         cudaFuncAttributeMaxDynamicSharedMemorySize,
                         SMEM_BYTES);
    poker_mlp_kernel<<<blocks, THREADS, SMEM_BYTES>>>(
        hole, board, W1, b1, W2, b2, out, B);
}

// round 7
// speedup vs baseline: 2.2831x; 2.2831x over previous
#include <cuda_runtime.h>
#include <cuda_bf16.h>
#include <cstdint>

// ===========================================================================
// Fused poker-feature MLP via mma.sync (HMMA bf16, 3-term split ~ fp32).
//   out[B,256] = relu(x @ W1 + b1) @ W2 + b2,  x = [hole|board|feats] (119)
//
// NOTE: tcgen05 is unavailable (harness compiles PTX at compute_103 base
// target; tcgen05 is sm_103a arch-specific). mma.sync.m16n8k16.bf16 is
// target-portable and uses the tensor pipe.
//
// prep kernels : cook W1^T / W2^T hi/lo bf16 splits into fragment-ordered
//                images so every B-operand load is one LDS.128.
// main kernel  : 128 rows/CTA. x bf16 fragments in smem; per 128-hidden
//                chunk: GEMM1 (3 terms) -> C1 regs -> relu/split epilogue
//                -> A2 fragment smem -> GEMM2 (2 N-halves x 3 terms) into
//                persistent C2 regs. cp.async double-buffered 32KB pieces.
// ===========================================================================

#define NT     512
#define BM     128
#define IND    119
#define HID    1024
#define OUTDIM 256

// smem byte offsets
#define A1H_B 0u        // [mb8][ks8][lane32][16B] = 32KB
#define A1L_B 32768u    // [mb8][ks2][lane32][16B] = 8KB (k 96..127 only)
#define A2H_B 40960u    // 32KB
#define A2L_B 73728u    // 32KB
#define BB_B  106496u   // 2 x 32KB piece slots
#define SMEMB 172032u

#define NPIECES 48      // 8 chunks x 6 pieces

// fragment-ordered weight images
__device__ __align__(16) unsigned char gW1frag[16 * 32768];  // [c][split]
__device__ __align__(16) unsigned char gW2frag[32 * 32768];  // [c][half][split]

// ---------------------------------------------------------------------------
__device__ __forceinline__ unsigned pack_bf16(float a, float b) {
    __nv_bfloat162 t = __floats2bfloat162_rn(a, b);
    return *(unsigned*)&t;
}
__device__ __forceinline__ float bf16rt(float a) {
    return __bfloat162float(__float2bfloat16(a));
}
__device__ __forceinline__ uint32_t smem_u32(const void* p) {
    uint32_t a;
    asm("{ .reg .u64 t; cvta.to.shared.u64 t, %1; cvt.u32.u64 %0, t; }"
        : "=r"(a) : "l"(p));
    return a;
}
__device__ __forceinline__ void mma16816(float c[4], const uint4& A,
                                         unsigned b0, unsigned b1) {
    asm volatile(
        "mma.sync.aligned.m16n8k16.row.col.f32.bf16.bf16.f32 "
        "{%0,%1,%2,%3}, {%4,%5,%6,%7}, {%8,%9}, {%0,%1,%2,%3};\n"
        : "+f"(c[0]), "+f"(c[1]), "+f"(c[2]), "+f"(c[3])
        : "r"(A.x), "r"(A.y), "r"(A.z), "r"(A.w), "r"(b0), "r"(b1));
}
#define CP_WAIT1() asm volatile("cp.async.wait_group 1;" ::: "memory")

// byte offset of element (row r, col cl) in an A-fragment region (8 mblks)
__device__ __forceinline__ uint32_t afrag_off(int r, int cl) {
    int mb = r >> 4, i = r & 15, ks = cl >> 4, jj = cl & 15;
    int lane = ((i & 7) << 2) + ((jj & 7) >> 1);
    int reg = (i >> 3) + ((jj >> 3) << 1);
    return ((((mb << 3) + ks) << 5) + lane) * 16u + (reg << 2) + ((jj & 1) << 1);
}
// same for the 2-kstep lo region (k 96..127)
__device__ __forceinline__ uint32_t lofrag_off(int r, int cl) {
    int mb = r >> 4, i = r & 15, ks = (cl >> 4) - 6, jj = cl & 15;
    int lane = ((i & 7) << 2) + ((jj & 7) >> 1);
    int reg = (i >> 3) + ((jj >> 3) << 1);
    return ((((mb << 1) + ks) << 5) + lane) * 16u + (reg << 2) + ((jj & 1) << 1);
}

// ---------------------------------------------------------------------------
// Prep: cook fragment images.  b32 q within a piece:
//   q = ((ks*8 + n16)*32 + lane)*4 + j ;  n8 = n16*2 + (j>>1), breg = j&1
//   k = ks*16 + (lane&3)*2 + breg*8 ;  n = n8*8 + (lane>>2)
//   b32 = pack(bf16 of (k), bf16 of (k+1))   [low = k]
// ---------------------------------------------------------------------------
__global__ void prep_w1(const float* __restrict__ W1) {
    int id = blockIdx.x * blockDim.x + threadIdx.x;
    if (id >= 16 * 8192) return;
    int pi = id >> 13, q = id & 8191;
    int c = pi >> 1, split = pi & 1;
    int ks = q >> 10, n16 = (q >> 7) & 7, lane = (q >> 2) & 31, j = q & 3;
    int n8 = n16 * 2 + (j >> 1), breg = j & 1;
    int k = ks * 16 + (lane & 3) * 2 + breg * 8;
    int n = n8 * 8 + (lane >> 2);
    float v0 = (k < IND)     ? W1[k * HID + c * 128 + n]       : 0.0f;
    float v1 = (k + 1 < IND) ? W1[(k + 1) * HID + c * 128 + n] : 0.0f;
    if (split) { v0 = v0 - bf16rt(v0); v1 = v1 - bf16rt(v1); }
    ((unsigned*)gW1frag)[pi * 8192 + q] = pack_bf16(v0, v1);
}
__global__ void prep_w2(const float* __restrict__ W2) {
    int id = blockIdx.x * blockDim.x + threadIdx.x;
    if (id >= 32 * 8192) return;
    int pi = id >> 13, q = id & 8191;
    int c = pi >> 2, half = (pi >> 1) & 1, split = pi & 1;
    int ks = q >> 10, n16 = (q >> 7) & 7, lane = (q >> 2) & 31, j = q & 3;
    int n8 = n16 * 2 + (j >> 1), breg = j & 1;
    int k = ks * 16 + (lane & 3) * 2 + breg * 8;
    int n = n8 * 8 + (lane >> 2);
    float v0 = W2[(c * 128 + k) * OUTDIM + half * 128 + n];
    float v1 = W2[(c * 128 + k + 1) * OUTDIM + half * 128 + n];
    if (split) { v0 = v0 - bf16rt(v0); v1 = v1 - bf16rt(v1); }
    ((unsigned*)gW2frag)[pi * 8192 + q] = pack_bf16(v0, v1);
}

// ---------------------------------------------------------------------------
__device__ __forceinline__ const unsigned char* piece_src(int p) {
    int c = p / 6, t = p % 6;
    if (t < 2) return gW1frag + (size_t)((c << 1) + t) * 32768u;
    return gW2frag + (size_t)((c << 2) + (t - 2)) * 32768u;
}
__device__ __forceinline__ void issue_piece(int p, uint32_t bb_u32, int tid) {
    if (p < NPIECES) {
        const unsigned char* src = piece_src(p) + tid * 64;
        uint32_t dst = bb_u32 + (uint32_t)(p & 1) * 32768u + (uint32_t)tid * 64u;
#pragma unroll
        for (int i = 0; i < 4; i++)
            asm volatile("cp.async.cg.shared.global [%0], [%1], 16;"
                         :: "r"(dst + i * 16), "l"(src + i * 16));
    }
    asm volatile("cp.async.commit_group;" ::: "memory");
}

// full-K GEMM term: C[2][4][4] += A(frags) * B(piece)
__device__ __forceinline__ void gemm_term(float C[2][4][4],
                                          const uint4* __restrict__ aF,
                                          const uint4* __restrict__ sb,
                                          int mb0, int n16a, int lane) {
#pragma unroll
    for (int ks = 0; ks < 8; ks++) {
        uint4 Be = sb[(ks * 8 + n16a) * 32 + lane];
        uint4 Bo = sb[(ks * 8 + n16a + 1) * 32 + lane];
        uint4 A0 = aF[(mb0 * 8 + ks) * 32 + lane];
        uint4 A1 = aF[((mb0 + 1) * 8 + ks) * 32 + lane];
        mma16816(C[0][0], A0, Be.x, Be.y);
        mma16816(C[0][1], A0, Be.z, Be.w);
        mma16816(C[0][2], A0, Bo.x, Bo.y);
        mma16816(C[0][3], A0, Bo.z, Bo.w);
        mma16816(C[1][0], A1, Be.x, Be.y);
        mma16816(C[1][1], A1, Be.z, Be.w);
        mma16816(C[1][2], A1, Bo.x, Bo.y);
        mma16816(C[1][3], A1, Bo.z, Bo.w);
    }
}
// GEMM1 x-lo term: only ksteps 6,7 live in the 2-kstep lo region
__device__ __forceinline__ void gemm_term_lo1(float C[2][4][4],
                                              const uint4* __restrict__ aL,
                                              const uint4* __restrict__ sb,
                                              int mb0, int n16a, int lane) {
#pragma unroll
    for (int ks = 6; ks < 8; ks++) {
        uint4 Be = sb[(ks * 8 + n16a) * 32 + lane];
        uint4 Bo = sb[(ks * 8 + n16a + 1) * 32 + lane];
        uint4 A0 = aL[(mb0 * 2 + (ks - 6)) * 32 + lane];
        uint4 A1 = aL[((mb0 + 1) * 2 + (ks - 6)) * 32 + lane];
        mma16816(C[0][0], A0, Be.x, Be.y);
        mma16816(C[0][1], A0, Be.z, Be.w);
        mma16816(C[0][2], A0, Bo.x, Bo.y);
        mma16816(C[0][3], A0, Bo.z, Bo.w);
        mma16816(C[1][0], A1, Be.x, Be.y);
        mma16816(C[1][1], A1, Be.z, Be.w);
        mma16816(C[1][2], A1, Bo.x, Bo.y);
        mma16816(C[1][3], A1, Bo.z, Bo.w);
    }
}

// ---------------------------------------------------------------------------
__global__ void __launch_bounds__(NT, 1)
mlp_hmma_kernel(const float* __restrict__ hole, const float* __restrict__ board,
                const float* __restrict__ b1g, const float* __restrict__ b2g,
                float* __restrict__ out, int Btot)
{
    extern __shared__ __align__(16) unsigned char smp[];
    const int tid = threadIdx.x;
    const int w = tid >> 5, lane = tid & 31;
    const int g = lane >> 2, tg = lane & 3;
    const int row0 = blockIdx.x * BM;

    const uint32_t sm_u = smem_u32(smp);
    uint4* A1h = (uint4*)(smp + A1H_B);
    uint4* A1l = (uint4*)(smp + A1L_B);
    uint4* A2h = (uint4*)(smp + A2H_B);
    uint4* A2l = (uint4*)(smp + A2L_B);

    // ---- zero A1 fragment regions (40KB) ----------------------------------
    {
        uint4 z = make_uint4(0, 0, 0, 0);
#pragma unroll 2
        for (int i = tid; i < 2560; i += NT) ((uint4*)smp)[i] = z;
    }
    __syncthreads();

    // ---- per-row features + card bits -> A1 fragments ---------------------
    if (tid < BM) {
        int r = tid, grow = row0 + r;
        if (grow < Btot) {
            const float* hp = hole + (size_t)grow * 52;
            const float* bp = board + (size_t)grow * 52;
            const __nv_bfloat16 one = __float2bfloat16(1.0f);
            int bsc[4] = {0, 0, 0, 0}, asc[4] = {0, 0, 0, 0};
            int bcount = 0, hcount = 0, pairs_b = 0, pairs_a = 0;
            bool trips_b = false, trips_a = false;
            int pb[17], pa[17];
#pragma unroll
            for (int rk = 0; rk < 13; rk++) {
                int b4 = 0, a4 = 0;
#pragma unroll
                for (int su = 0; su < 4; su++) {
                    int c = rk * 4 + su;
                    int hv = (hp[c] != 0.0f);
                    int bv = (bp[c] != 0.0f);
                    if (hv) *(__nv_bfloat16*)(smp + A1H_B + afrag_off(r, c)) = one;
                    if (bv) *(__nv_bfloat16*)(smp + A1H_B + afrag_off(r, 52 + c)) = one;
                    b4 += bv; a4 += hv + bv;
                    bcount += bv; hcount += hv;
                    bsc[su] += bv; asc[su] += hv + bv;
                }
                pairs_b += (b4 >= 2); trips_b |= (b4 >= 3);
                pairs_a += (a4 >= 2); trips_a |= (a4 >= 3);
                pb[rk] = (b4 > 0); pa[rk] = (a4 > 0);
            }
#pragma unroll
            for (int i = 13; i < 17; i++) { pb[i] = 0; pa[i] = 0; }

            float strength = trips_b ? 0.8f
                           : (pairs_b >= 2 ? 0.6f : (pairs_b >= 1 ? 0.4f : 0.2f));
            if (bcount == 0) strength = 0.0f;
            int maxbsc = max(max(bsc[0], bsc[1]), max(bsc[2], bsc[3]));
            float flush_b = (maxbsc >= 3 && bcount > 0) ? 1.0f : 0.0f;
            bool sb = false;
#pragma unroll
            for (int j = 0; j < 13; j++) {
                int ww = pb[j] + pb[j + 1] + pb[j + 2] + pb[j + 3] + pb[j + 4];
                if (ww >= 3) sb = true;
            }
            float straight_b = (sb && bcount > 0) ? 1.0f : 0.0f;
            float valid = (hcount >= 2 && bcount >= 1) ? 1.0f : 0.0f;
            int msc = max(max(asc[0], asc[1]), max(asc[2], asc[3]));
            float flush_draw = (msc == 4) ? 1.0f : 0.0f;
            float flush_outs = fmaxf(0.0f, 13.0f - (float)msc) / 13.0f;
            bool found = false; int c4_at = 0;
#pragma unroll
            for (int j = 0; j < 13; j++) {
                int c5 = pa[j] + pa[j + 1] + pa[j + 2] + pa[j + 3] + pa[j + 4];
                bool q = (pa[j] > 0) && (c5 >= 4);
                if (q && !found) {
                    found = true;
                    c4_at = pa[j] + pa[j + 1] + pa[j + 2] + pa[j + 3];
                }
            }
            float sd = found ? 1.0f : 0.0f;
            float so = found ? (c4_at >= 4 ? 0.4f : 0.2f) : 0.0f;
            float total_outs = flush_draw * flush_outs * 9.0f + sd * so * 8.0f;
            float remaining = 52.0f - (float)(hcount + bcount);
            float equity = (remaining > 0.0f)
                ? fminf(1.0f, total_outs / fmaxf(remaining, 1.0f)) : 0.0f;

            float feats[15];
            feats[0] = strength; feats[1] = flush_b; feats[2] = straight_b;
            feats[3] = (bcount == 0) ? 1.0f : 0.0f;
            feats[4] = (bcount == 3) ? 1.0f : 0.0f;
            feats[5] = (bcount == 4) ? 1.0f : 0.0f;
            feats[6] = (bcount == 5) ? 1.0f : 0.0f;
            feats[7]  = valid * flush_draw;
            feats[8]  = valid * flush_outs;
            feats[9]  = valid * sd;
            feats[10] = valid * so;
            feats[11] = valid * equity;
            feats[12] = valid * ((pairs_a >= 1) ? 1.0f : 0.0f);
            feats[13] = valid * (trips_a ? 1.0f : 0.0f);
            feats[14] = valid * ((pairs_a >= 2) ? 1.0f : 0.0f);
#pragma unroll
            for (int t = 0; t < 15; t++) {
                float f = feats[t];
                float fh = bf16rt(f);
                int cl = 104 + t;
                *(__nv_bfloat16*)(smp + A1H_B + afrag_off(r, cl)) = __float2bfloat16(f);
                *(__nv_bfloat16*)(smp + A1L_B + lofrag_off(r, cl)) =
                    __float2bfloat16(f - fh);
            }
        }
    }

    // ---- pipeline prologue ------------------------------------------------
    const uint32_t bb_u = sm_u + BB_B;
    issue_piece(0, bb_u, tid);
    issue_piece(1, bb_u, tid);

    const int mb0 = (w >> 2) * 2;   // warp M-range: rows mb0*16 .. +32
    const int nq  = (w & 3);        // warp N-range: n8 blocks nq*4 .. +4
    const int n16a = nq * 2;

    float C2[2][2][4][4];           // [half][mbi][j][reg]
#pragma unroll
    for (int h = 0; h < 2; h++)
#pragma unroll
        for (int mi = 0; mi < 2; mi++)
#pragma unroll
            for (int j = 0; j < 4; j++)
#pragma unroll
                for (int q = 0; q < 4; q++) C2[h][mi][j][q] = 0.0f;

    int p = 0;
    for (int c = 0; c < 8; c++) {
        float C1[2][4][4];
#pragma unroll
        for (int mi = 0; mi < 2; mi++)
#pragma unroll
            for (int j = 0; j < 4; j++)
#pragma unroll
                for (int q = 0; q < 4; q++) C1[mi][j][q] = 0.0f;

        // piece 0: W1 hi  -> AhBh (full K) + AlBh (ks 6,7)
        CP_WAIT1(); __syncthreads();
        {
            const uint4* sb = (const uint4*)(smp + BB_B + (p & 1) * 32768u);
            gemm_term(C1, A1h, sb, mb0, n16a, lane);
            gemm_term_lo1(C1, A1l, sb, mb0, n16a, lane);
        }
        __syncthreads(); issue_piece(p + 2, bb_u, tid); p++;

        // piece 1: W1 lo  -> AhBl ; then epilogue C1 -> A2 fragments
        CP_WAIT1(); __syncthreads();
        {
            const uint4* sb = (const uint4*)(smp + BB_B + (p & 1) * 32768u);
            gemm_term(C1, A1h, sb, mb0, n16a, lane);
        }
        // epilogue: add b1, relu, bf16 hi/lo split, store as A2 fragments
#pragma unroll
        for (int mi = 0; mi < 2; mi++) {
#pragma unroll
            for (int jp = 0; jp < 2; jp++) {
                int ksg = nq * 2 + jp;
                int n0e = (nq * 4 + 2 * jp) * 8 + tg * 2;
                float2 b1e = *(const float2*)(b1g + c * 128 + n0e);
                float2 b1o = *(const float2*)(b1g + c * 128 + n0e + 8);
                float* fe = C1[mi][2 * jp];
                float* fo = C1[mi][2 * jp + 1];
                float e0 = fmaxf(fe[0] + b1e.x, 0.0f);
                float e1 = fmaxf(fe[1] + b1e.y, 0.0f);
                float e2 = fmaxf(fe[2] + b1e.x, 0.0f);
                float e3 = fmaxf(fe[3] + b1e.y, 0.0f);
                float o0 = fmaxf(fo[0] + b1o.x, 0.0f);
                float o1 = fmaxf(fo[1] + b1o.y, 0.0f);
                float o2 = fmaxf(fo[2] + b1o.x, 0.0f);
                float o3 = fmaxf(fo[3] + b1o.y, 0.0f);
                uint4 hv, lv;
                hv.x = pack_bf16(e0, e1); hv.y = pack_bf16(e2, e3);
                hv.z = pack_bf16(o0, o1); hv.w = pack_bf16(o2, o3);
                lv.x = pack_bf16(e0 - bf16rt(e0), e1 - bf16rt(e1));
                lv.y = pack_bf16(e2 - bf16rt(e2), e3 - bf16rt(e3));
                lv.z = pack_bf16(o0 - bf16rt(o0), o1 - bf16rt(o1));
                lv.w = pack_bf16(o2 - bf16rt(o2), o3 - bf16rt(o3));
                int idx = ((mb0 + mi) * 8 + ksg) * 32 + lane;
                A2h[idx] = hv;
                A2l[idx] = lv;
            }
        }
        __syncthreads(); issue_piece(p + 2, bb_u, tid); p++;

        // pieces 2..5: GEMM2, halves 0 and 1, terms (AhBh+AlBh) then AhBl
#pragma unroll
        for (int h = 0; h < 2; h++) {
            CP_WAIT1(); __syncthreads();
            {
                const uint4* sb = (const uint4*)(smp + BB_B + (p & 1) * 32768u);
                gemm_term(C2[h], A2h, sb, mb0, n16a, lane);
                gemm_term(C2[h], A2l, sb, mb0, n16a, lane);
            }
            __syncthreads(); issue_piece(p + 2, bb_u, tid); p++;

            CP_WAIT1(); __syncthreads();
            {
                const uint4* sb = (const uint4*)(smp + BB_B + (p & 1) * 32768u);
                gemm_term(C2[h], A2h, sb, mb0, n16a, lane);
            }
            __syncthreads(); issue_piece(p + 2, bb_u, tid); p++;
        }
    }

    // ---- final epilogue: C2 + b2 -> out -----------------------------------
#pragma unroll
    for (int h = 0; h < 2; h++) {
#pragma unroll
        for (int mi = 0; mi < 2; mi++) {
            int r0 = row0 + (mb0 + mi) * 16 + g;
#pragma unroll
            for (int j = 0; j < 4; j++) {
                int n0 = h * 128 + (nq * 4 + j) * 8 + tg * 2;
                float2 bb = *(const float2*)(b2g + n0);
                float* cc = C2[h][mi][j];
                if (r0 < Btot) {
                    float2 v = make_float2(cc[0] + bb.x, cc[1] + bb.y);
                    *(float2*)(out + (size_t)r0 * OUTDIM + n0) = v;
                }
                if (r0 + 8 < Btot) {
                    float2 v = make_float2(cc[2] + bb.x, cc[3] + bb.y);
                    *(float2*)(out + (size_t)(r0 + 8) * OUTDIM + n0) = v;
                }
            }
        }
    }
}

// ---------------------------------------------------------------------------
extern "C" void kernel_launch(void* const* d_in, const int* in_sizes, int n_in,
                              void* d_out, int out_size)
{
    const float* hole  = (const float*)d_in[0];
    const float* board = (const float*)d_in[1];
    const float* W1    = (const float*)d_in[2];
    const float* b1    = (const float*)d_in[3];
    const float* W2    = (const float*)d_in[4];
    const float* b2    = (const float*)d_in[5];
    float* out = (float*)d_out;

    int B = in_sizes[0] / 52;
    int blocks = (B + BM - 1) / BM;

    prep_w1<<<(16 * 8192 + 255) / 256, 256>>>(W1);
    prep_w2<<<(32 * 8192 + 255) / 256, 256>>>(W2);

    cudaFuncSetAttribute(mlp_hmma_kernel,
                         cudaFuncAttributeMaxDynamicSharedMemorySize, SMEMB);
    mlp_hmma_kernel<<<blocks, NT, SMEMB>>>(hole, board, b1, b2, out, B);
}

// round 8
// speedup vs baseline: 4.1850x; 1.8330x over previous
#include <cuda_runtime.h>
#include <cuda_bf16.h>
#include <cuda_fp16.h>
#include <cstdint>

// ===========================================================================
// Fused poker-feature MLP via mma.sync (HMMA fp16, 2-term A-split).
//   out[B,256] = relu(x @ W1 + b1) @ W2 + b2,  x = [hole|board|feats] (119)
//
// fp16 (11-bit mantissa) 2-term scheme:  A*B ~= Ah*Bh + Al*Bh   (B hi only)
//   predicted aggregate rel err ~4e-4 (calibrated against R6's measured
//   6.2e-6 for the bf16 3-term scheme).
// GEMM1: x-lo has only the 15 feature columns (k-steps 6,7).
// Pieces per chunk: W1h, W2half0-h, W2half1-h  (24 total, cp.async 2-deep).
// ===========================================================================

#define NT     512
#define BM     128
#define IND    119
#define HID    1024
#define OUTDIM 256

// smem byte offsets
#define A1H_B 0u        // [mb8][ks8][lane32][16B] = 32KB
#define A1L_B 32768u    // [mb8][ks2][lane32][16B] = 8KB (k 96..127 only)
#define A2H_B 40960u    // 32KB
#define A2L_B 73728u    // 32KB
#define BB_B  106496u   // 2 x 32KB piece slots
#define SMEMB 172032u

#define NPIECES 24      // 8 chunks x 3 pieces

// fragment-ordered weight images (fp16 hi only)
__device__ __align__(16) unsigned char gW1frag[8 * 32768];   // [c]
__device__ __align__(16) unsigned char gW2frag[16 * 32768];  // [c][half]

// ---------------------------------------------------------------------------
__device__ __forceinline__ unsigned pack_f16(float a, float b) {
    __half2 t = __floats2half2_rn(a, b);
    return *(unsigned*)&t;
}
__device__ __forceinline__ float f16rt(float a) {
    return __half2float(__float2half_rn(a));
}
__device__ __forceinline__ uint32_t smem_u32(const void* p) {
    uint32_t a;
    asm("{ .reg .u64 t; cvta.to.shared.u64 t, %1; cvt.u32.u64 %0, t; }"
        : "=r"(a) : "l"(p));
    return a;
}
__device__ __forceinline__ void mma16816(float c[4], const uint4& A,
                                         unsigned b0, unsigned b1) {
    asm volatile(
        "mma.sync.aligned.m16n8k16.row.col.f32.f16.f16.f32 "
        "{%0,%1,%2,%3}, {%4,%5,%6,%7}, {%8,%9}, {%0,%1,%2,%3};\n"
        : "+f"(c[0]), "+f"(c[1]), "+f"(c[2]), "+f"(c[3])
        : "r"(A.x), "r"(A.y), "r"(A.z), "r"(A.w), "r"(b0), "r"(b1));
}
#define CP_WAIT1() asm volatile("cp.async.wait_group 1;" ::: "memory")

// byte offset of element (row r, col cl) in an A-fragment region (8 mblks)
__device__ __forceinline__ uint32_t afrag_off(int r, int cl) {
    int mb = r >> 4, i = r & 15, ks = cl >> 4, jj = cl & 15;
    int lane = ((i & 7) << 2) + ((jj & 7) >> 1);
    int reg = (i >> 3) + ((jj >> 3) << 1);
    return ((((mb << 3) + ks) << 5) + lane) * 16u + (reg << 2) + ((jj & 1) << 1);
}
// 2-kstep lo region (k 96..127)
__device__ __forceinline__ uint32_t lofrag_off(int r, int cl) {
    int mb = r >> 4, i = r & 15, ks = (cl >> 4) - 6, jj = cl & 15;
    int lane = ((i & 7) << 2) + ((jj & 7) >> 1);
    int reg = (i >> 3) + ((jj >> 3) << 1);
    return ((((mb << 1) + ks) << 5) + lane) * 16u + (reg << 2) + ((jj & 1) << 1);
}

// ---------------------------------------------------------------------------
// Prep: cook fp16 fragment images. b32 q within a piece:
//   q = ((ks*8 + n16)*32 + lane)*4 + j ; n8 = n16*2 + (j>>1), breg = j&1
//   k = ks*16 + (lane&3)*2 + breg*8 ;  n = n8*8 + (lane>>2)
// ---------------------------------------------------------------------------
__global__ void prep_w1(const float* __restrict__ W1) {
    int id = blockIdx.x * blockDim.x + threadIdx.x;
    if (id >= 8 * 8192) return;
    int c = id >> 13, q = id & 8191;
    int ks = q >> 10, n16 = (q >> 7) & 7, lane = (q >> 2) & 31, j = q & 3;
    int n8 = n16 * 2 + (j >> 1), breg = j & 1;
    int k = ks * 16 + (lane & 3) * 2 + breg * 8;
    int n = n8 * 8 + (lane >> 2);
    float v0 = (k < IND)     ? W1[k * HID + c * 128 + n]       : 0.0f;
    float v1 = (k + 1 < IND) ? W1[(k + 1) * HID + c * 128 + n] : 0.0f;
    ((unsigned*)gW1frag)[c * 8192 + q] = pack_f16(v0, v1);
}
__global__ void prep_w2(const float* __restrict__ W2) {
    int id = blockIdx.x * blockDim.x + threadIdx.x;
    if (id >= 16 * 8192) return;
    int pi = id >> 13, q = id & 8191;
    int c = pi >> 1, half = pi & 1;
    int ks = q >> 10, n16 = (q >> 7) & 7, lane = (q >> 2) & 31, j = q & 3;
    int n8 = n16 * 2 + (j >> 1), breg = j & 1;
    int k = ks * 16 + (lane & 3) * 2 + breg * 8;
    int n = n8 * 8 + (lane >> 2);
    float v0 = W2[(c * 128 + k) * OUTDIM + half * 128 + n];
    float v1 = W2[(c * 128 + k + 1) * OUTDIM + half * 128 + n];
    ((unsigned*)gW2frag)[pi * 8192 + q] = pack_f16(v0, v1);
}

// ---------------------------------------------------------------------------
__device__ __forceinline__ const unsigned char* piece_src(int p) {
    int c = p / 3, t = p % 3;
    if (t == 0) return gW1frag + (size_t)c * 32768u;
    return gW2frag + (size_t)((c << 1) + (t - 1)) * 32768u;
}
__device__ __forceinline__ void issue_piece(int p, uint32_t bb_u32, int tid) {
    if (p < NPIECES) {
        const unsigned char* src = piece_src(p) + tid * 64;
        uint32_t dst = bb_u32 + (uint32_t)(p & 1) * 32768u + (uint32_t)tid * 64u;
#pragma unroll
        for (int i = 0; i < 4; i++)
            asm volatile("cp.async.cg.shared.global [%0], [%1], 16;"
                         :: "r"(dst + i * 16), "l"(src + i * 16));
    }
    asm volatile("cp.async.commit_group;" ::: "memory");
}

// full-K single-A term: C[2][4][4] += A * B
__device__ __forceinline__ void gemm_term(float C[2][4][4],
                                          const uint4* __restrict__ aF,
                                          const uint4* __restrict__ sb,
                                          int mb0, int n16a, int lane) {
#pragma unroll
    for (int ks = 0; ks < 8; ks++) {
        uint4 Be = sb[(ks * 8 + n16a) * 32 + lane];
        uint4 Bo = sb[(ks * 8 + n16a + 1) * 32 + lane];
        uint4 A0 = aF[(mb0 * 8 + ks) * 32 + lane];
        uint4 A1 = aF[((mb0 + 1) * 8 + ks) * 32 + lane];
        mma16816(C[0][0], A0, Be.x, Be.y);
        mma16816(C[0][1], A0, Be.z, Be.w);
        mma16816(C[0][2], A0, Bo.x, Bo.y);
        mma16816(C[0][3], A0, Bo.z, Bo.w);
        mma16816(C[1][0], A1, Be.x, Be.y);
        mma16816(C[1][1], A1, Be.z, Be.w);
        mma16816(C[1][2], A1, Bo.x, Bo.y);
        mma16816(C[1][3], A1, Bo.z, Bo.w);
    }
}
// dual-A term (hi+lo share one B load): C += Ah*B + Al*B
__device__ __forceinline__ void gemm_term_dual(float C[2][4][4],
                                               const uint4* __restrict__ aH,
                                               const uint4* __restrict__ aL,
                                               const uint4* __restrict__ sb,
                                               int mb0, int n16a, int lane) {
#pragma unroll
    for (int ks = 0; ks < 8; ks++) {
        uint4 Be = sb[(ks * 8 + n16a) * 32 + lane];
        uint4 Bo = sb[(ks * 8 + n16a + 1) * 32 + lane];
        uint4 A0 = aH[(mb0 * 8 + ks) * 32 + lane];
        uint4 A1 = aH[((mb0 + 1) * 8 + ks) * 32 + lane];
        mma16816(C[0][0], A0, Be.x, Be.y);
        mma16816(C[0][1], A0, Be.z, Be.w);
        mma16816(C[0][2], A0, Bo.x, Bo.y);
        mma16816(C[0][3], A0, Bo.z, Bo.w);
        mma16816(C[1][0], A1, Be.x, Be.y);
        mma16816(C[1][1], A1, Be.z, Be.w);
        mma16816(C[1][2], A1, Bo.x, Bo.y);
        mma16816(C[1][3], A1, Bo.z, Bo.w);
        uint4 L0 = aL[(mb0 * 8 + ks) * 32 + lane];
        uint4 L1 = aL[((mb0 + 1) * 8 + ks) * 32 + lane];
        mma16816(C[0][0], L0, Be.x, Be.y);
        mma16816(C[0][1], L0, Be.z, Be.w);
        mma16816(C[0][2], L0, Bo.x, Bo.y);
        mma16816(C[0][3], L0, Bo.z, Bo.w);
        mma16816(C[1][0], L1, Be.x, Be.y);
        mma16816(C[1][1], L1, Be.z, Be.w);
        mma16816(C[1][2], L1, Bo.x, Bo.y);
        mma16816(C[1][3], L1, Bo.z, Bo.w);
    }
}
// GEMM1 x-lo term: only ksteps 6,7 live in the 2-kstep lo region
__device__ __forceinline__ void gemm_term_lo1(float C[2][4][4],
                                              const uint4* __restrict__ aL,
                                              const uint4* __restrict__ sb,
                                              int mb0, int n16a, int lane) {
#pragma unroll
    for (int ks = 6; ks < 8; ks++) {
        uint4 Be = sb[(ks * 8 + n16a) * 32 + lane];
        uint4 Bo = sb[(ks * 8 + n16a + 1) * 32 + lane];
        uint4 A0 = aL[(mb0 * 2 + (ks - 6)) * 32 + lane];
        uint4 A1 = aL[((mb0 + 1) * 2 + (ks - 6)) * 32 + lane];
        mma16816(C[0][0], A0, Be.x, Be.y);
        mma16816(C[0][1], A0, Be.z, Be.w);
        mma16816(C[0][2], A0, Bo.x, Bo.y);
        mma16816(C[0][3], A0, Bo.z, Bo.w);
        mma16816(C[1][0], A1, Be.x, Be.y);
        mma16816(C[1][1], A1, Be.z, Be.w);
        mma16816(C[1][2], A1, Bo.x, Bo.y);
        mma16816(C[1][3], A1, Bo.z, Bo.w);
    }
}

// ---------------------------------------------------------------------------
__global__ void __launch_bounds__(NT, 1)
mlp_hmma_kernel(const float* __restrict__ hole, const float* __restrict__ board,
                const float* __restrict__ b1g, const float* __restrict__ b2g,
                float* __restrict__ out, int Btot)
{
    extern __shared__ __align__(16) unsigned char smp[];
    const int tid = threadIdx.x;
    const int w = tid >> 5, lane = tid & 31;
    const int g = lane >> 2, tg = lane & 3;
    const int row0 = blockIdx.x * BM;

    const uint32_t sm_u = smem_u32(smp);
    uint4* A1h = (uint4*)(smp + A1H_B);
    uint4* A1l = (uint4*)(smp + A1L_B);
    uint4* A2h = (uint4*)(smp + A2H_B);
    uint4* A2l = (uint4*)(smp + A2L_B);

    // ---- zero A1 fragment regions (40KB) ----------------------------------
    {
        uint4 z = make_uint4(0, 0, 0, 0);
#pragma unroll 2
        for (int i = tid; i < 2560; i += NT) ((uint4*)smp)[i] = z;
    }
    __syncthreads();

    // ---- per-row features + card bits -> A1 fragments ---------------------
    if (tid < BM) {
        int r = tid, grow = row0 + r;
        if (grow < Btot) {
            const float* hp = hole + (size_t)grow * 52;
            const float* bp = board + (size_t)grow * 52;
            const __half one = __float2half_rn(1.0f);
            int bsc[4] = {0, 0, 0, 0}, asc[4] = {0, 0, 0, 0};
            int bcount = 0, hcount = 0, pairs_b = 0, pairs_a = 0;
            bool trips_b = false, trips_a = false;
            int pb[17], pa[17];
#pragma unroll
            for (int rk = 0; rk < 13; rk++) {
                int b4 = 0, a4 = 0;
#pragma unroll
                for (int su = 0; su < 4; su++) {
                    int c = rk * 4 + su;
                    int hv = (hp[c] != 0.0f);
                    int bv = (bp[c] != 0.0f);
                    if (hv) *(__half*)(smp + A1H_B + afrag_off(r, c)) = one;
                    if (bv) *(__half*)(smp + A1H_B + afrag_off(r, 52 + c)) = one;
                    b4 += bv; a4 += hv + bv;
                    bcount += bv; hcount += hv;
                    bsc[su] += bv; asc[su] += hv + bv;
                }
                pairs_b += (b4 >= 2); trips_b |= (b4 >= 3);
                pairs_a += (a4 >= 2); trips_a |= (a4 >= 3);
                pb[rk] = (b4 > 0); pa[rk] = (a4 > 0);
            }
#pragma unroll
            for (int i = 13; i < 17; i++) { pb[i] = 0; pa[i] = 0; }

            float strength = trips_b ? 0.8f
                           : (pairs_b >= 2 ? 0.6f : (pairs_b >= 1 ? 0.4f : 0.2f));
            if (bcount == 0) strength = 0.0f;
            int maxbsc = max(max(bsc[0], bsc[1]), max(bsc[2], bsc[3]));
            float flush_b = (maxbsc >= 3 && bcount > 0) ? 1.0f : 0.0f;
            bool sb = false;
#pragma unroll
            for (int j = 0; j < 13; j++) {
                int ww = pb[j] + pb[j + 1] + pb[j + 2] + pb[j + 3] + pb[j + 4];
                if (ww >= 3) sb = true;
            }
            float straight_b = (sb && bcount > 0) ? 1.0f : 0.0f;
            float valid = (hcount >= 2 && bcount >= 1) ? 1.0f : 0.0f;
            int msc = max(max(asc[0], asc[1]), max(asc[2], asc[3]));
            float flush_draw = (msc == 4) ? 1.0f : 0.0f;
            float flush_outs = fmaxf(0.0f, 13.0f - (float)msc) / 13.0f;
            bool found = false; int c4_at = 0;
#pragma unroll
            for (int j = 0; j < 13; j++) {
                int c5 = pa[j] + pa[j + 1] + pa[j + 2] + pa[j + 3] + pa[j + 4];
                bool q = (pa[j] > 0) && (c5 >= 4);
                if (q && !found) {
                    found = true;
                    c4_at = pa[j] + pa[j + 1] + pa[j + 2] + pa[j + 3];
                }
            }
            float sd = found ? 1.0f : 0.0f;
            float so = found ? (c4_at >= 4 ? 0.4f : 0.2f) : 0.0f;
            float total_outs = flush_draw * flush_outs * 9.0f + sd * so * 8.0f;
            float remaining = 52.0f - (float)(hcount + bcount);
            float equity = (remaining > 0.0f)
                ? fminf(1.0f, total_outs / fmaxf(remaining, 1.0f)) : 0.0f;

            float feats[15];
            feats[0] = strength; feats[1] = flush_b; feats[2] = straight_b;
            feats[3] = (bcount == 0) ? 1.0f : 0.0f;
            feats[4] = (bcount == 3) ? 1.0f : 0.0f;
            feats[5] = (bcount == 4) ? 1.0f : 0.0f;
            feats[6] = (bcount == 5) ? 1.0f : 0.0f;
            feats[7]  = valid * flush_draw;
            feats[8]  = valid * flush_outs;
            feats[9]  = valid * sd;
            feats[10] = valid * so;
            feats[11] = valid * equity;
            feats[12] = valid * ((pairs_a >= 1) ? 1.0f : 0.0f);
            feats[13] = valid * (trips_a ? 1.0f : 0.0f);
            feats[14] = valid * ((pairs_a >= 2) ? 1.0f : 0.0f);
#pragma unroll
            for (int t = 0; t < 15; t++) {
                float f = feats[t];
                float fh = f16rt(f);
                int cl = 104 + t;
                *(__half*)(smp + A1H_B + afrag_off(r, cl)) = __float2half_rn(f);
                *(__half*)(smp + A1L_B + lofrag_off(r, cl)) =
                    __float2half_rn(f - fh);
            }
        }
    }

    // ---- pipeline prologue ------------------------------------------------
    const uint32_t bb_u = sm_u + BB_B;
    issue_piece(0, bb_u, tid);
    issue_piece(1, bb_u, tid);

    const int mb0 = (w >> 2) * 2;   // warp M-range: rows mb0*16 .. +32
    const int nq  = (w & 3);        // warp N-range: n8 blocks nq*4 .. +4
    const int n16a = nq * 2;

    float C2[2][2][4][4];           // [half][mbi][j][reg]
#pragma unroll
    for (int h = 0; h < 2; h++)
#pragma unroll
        for (int mi = 0; mi < 2; mi++)
#pragma unroll
            for (int j = 0; j < 4; j++)
#pragma unroll
                for (int q = 0; q < 4; q++) C2[h][mi][j][q] = 0.0f;

    int p = 0;
    for (int c = 0; c < 8; c++) {
        float C1[2][4][4];
#pragma unroll
        for (int mi = 0; mi < 2; mi++)
#pragma unroll
            for (int j = 0; j < 4; j++)
#pragma unroll
                for (int q = 0; q < 4; q++) C1[mi][j][q] = 0.0f;

        // piece t=0: W1 hi  -> Ah*B (full K) + Al*B (ks 6,7)
        CP_WAIT1(); __syncthreads();
        {
            const uint4* sb = (const uint4*)(smp + BB_B + (p & 1) * 32768u);
            gemm_term(C1, A1h, sb, mb0, n16a, lane);
            gemm_term_lo1(C1, A1l, sb, mb0, n16a, lane);
        }
        __syncthreads(); issue_piece(p + 2, bb_u, tid); p++;

        // epilogue: add b1, relu, fp16 hi/lo split, store as A2 fragments
#pragma unroll
        for (int mi = 0; mi < 2; mi++) {
#pragma unroll
            for (int jp = 0; jp < 2; jp++) {
                int ksg = nq * 2 + jp;
                int n0e = (nq * 4 + 2 * jp) * 8 + tg * 2;
                float2 b1e = *(const float2*)(b1g + c * 128 + n0e);
                float2 b1o = *(const float2*)(b1g + c * 128 + n0e + 8);
                float* fe = C1[mi][2 * jp];
                float* fo = C1[mi][2 * jp + 1];
                float e0 = fmaxf(fe[0] + b1e.x, 0.0f);
                float e1 = fmaxf(fe[1] + b1e.y, 0.0f);
                float e2 = fmaxf(fe[2] + b1e.x, 0.0f);
                float e3 = fmaxf(fe[3] + b1e.y, 0.0f);
                float o0 = fmaxf(fo[0] + b1o.x, 0.0f);
                float o1 = fmaxf(fo[1] + b1o.y, 0.0f);
                float o2 = fmaxf(fo[2] + b1o.x, 0.0f);
                float o3 = fmaxf(fo[3] + b1o.y, 0.0f);
                uint4 hv, lv;
                hv.x = pack_f16(e0, e1); hv.y = pack_f16(e2, e3);
                hv.z = pack_f16(o0, o1); hv.w = pack_f16(o2, o3);
                lv.x = pack_f16(e0 - f16rt(e0), e1 - f16rt(e1));
                lv.y = pack_f16(e2 - f16rt(e2), e3 - f16rt(e3));
                lv.z = pack_f16(o0 - f16rt(o0), o1 - f16rt(o1));
                lv.w = pack_f16(o2 - f16rt(o2), o3 - f16rt(o3));
                int idx = ((mb0 + mi) * 8 + ksg) * 32 + lane;
                A2h[idx] = hv;
                A2l[idx] = lv;
            }
        }

        // pieces t=1,2: GEMM2 halves, both A terms share one B piece
#pragma unroll
        for (int h = 0; h < 2; h++) {
            CP_WAIT1(); __syncthreads();
            {
                const uint4* sb = (const uint4*)(smp + BB_B + (p & 1) * 32768u);
                gemm_term_dual(C2[h], A2h, A2l, sb, mb0, n16a, lane);
            }
            __syncthreads(); issue_piece(p + 2, bb_u, tid); p++;
        }
    }

    // ---- final epilogue: C2 + b2 -> out -----------------------------------
#pragma unroll
    for (int h = 0; h < 2; h++) {
#pragma unroll
        for (int mi = 0; mi < 2; mi++) {
            int r0 = row0 + (mb0 + mi) * 16 + g;
#pragma unroll
            for (int j = 0; j < 4; j++) {
                int n0 = h * 128 + (nq * 4 + j) * 8 + tg * 2;
                float2 bb = *(const float2*)(b2g + n0);
                float* cc = C2[h][mi][j];
                if (r0 < Btot) {
                    float2 v = make_float2(cc[0] + bb.x, cc[1] + bb.y);
                    *(float2*)(out + (size_t)r0 * OUTDIM + n0) = v;
                }
                if (r0 + 8 < Btot) {
                    float2 v = make_float2(cc[2] + bb.x, cc[3] + bb.y);
                    *(float2*)(out + (size_t)(r0 + 8) * OUTDIM + n0) = v;
                }
            }
        }
    }
}

// ---------------------------------------------------------------------------
extern "C" void kernel_launch(void* const* d_in, const int* in_sizes, int n_in,
                              void* d_out, int out_size)
{
    const float* hole  = (const float*)d_in[0];
    const float* board = (const float*)d_in[1];
    const float* W1    = (const float*)d_in[2];
    const float* b1    = (const float*)d_in[3];
    const float* W2    = (const float*)d_in[4];
    const float* b2    = (const float*)d_in[5];
    float* out = (float*)d_out;

    int B = in_sizes[0] / 52;
    int blocks = (B + BM - 1) / BM;

    prep_w1<<<(8 * 8192 + 255) / 256, 256>>>(W1);
    prep_w2<<<(16 * 8192 + 255) / 256, 256>>>(W2);

    cudaFuncSetAttribute(mlp_hmma_kernel,
                         cudaFuncAttributeMaxDynamicSharedMemorySize, SMEMB);
    mlp_hmma_kernel<<<blocks, NT, SMEMB>>>(hole, board, b1, b2, out, B);
}